// round 3
// baseline (speedup 1.0000x reference)
#include <cuda_runtime.h>
#include <cstdint>

#define N_PTS   16384
#define B_SZ    8
#define NPT     512
#define KNB     32
#define NCH     128
#define R2      0.04f

// ---------------- device scratch (no runtime allocation allowed) ----------------
__device__ int   g_cents[B_SZ * NPT];          // selected FPS indices
__device__ float g_n2   [B_SZ * N_PTS];        // per-point squared norms
__device__ int   g_idx  [B_SZ * NPT * KNB];    // ball-query neighbor lists

// ---------------- packed f32x2 helpers (two independent IEEE-rn ops) ------------
__device__ __forceinline__ unsigned long long f2_add(unsigned long long a, unsigned long long b) {
    unsigned long long r; asm("add.rn.f32x2 %0, %1, %2;" : "=l"(r) : "l"(a), "l"(b)); return r;
}
__device__ __forceinline__ unsigned long long f2_mul(unsigned long long a, unsigned long long b) {
    unsigned long long r; asm("mul.rn.f32x2 %0, %1, %2;" : "=l"(r) : "l"(a), "l"(b)); return r;
}
__device__ __forceinline__ unsigned long long f2_pack(float lo, float hi) {
    unsigned long long r; asm("mov.b64 %0, {%1, %2};" : "=l"(r) : "f"(lo), "f"(hi)); return r;
}
__device__ __forceinline__ void f2_unpack(float& lo, float& hi, unsigned long long v) {
    asm("mov.b64 {%0, %1}, %2;" : "=f"(lo), "=f"(hi) : "l"(v));
}

// =================================================================================
// Kernel 1: farthest point sampling — one CTA per batch, 1024 threads, 16 pts/thread
// x,y packed in registers (f32x2), z in skewed shared memory, dists in registers.
// Exact arithmetic: d = ((dx*dx + dy*dy) + dz*dz), plain rn mul/add (no FMA).
// argmax = first max index (strictly-greater within thread, min-idx tie-break across).
// Also emits new_xyz rows and per-point squared norms.
// =================================================================================
extern __shared__ float zsh[];  // N_PTS + 2*(N_PTS/32) floats

__global__ void __launch_bounds__(1024, 1)
fps_kernel(const float* __restrict__ xyz, float* __restrict__ out_newxyz)
{
    const int b = blockIdx.x;
    const int t = threadIdx.x;
    const float* X = xyz + (size_t)b * N_PTS * 3;

    __shared__ float s_c[3];
    __shared__ float s_val[32];
    __shared__ int   s_idx[32];

    unsigned long long xq[8], yq[8];
    float pd[16];
    const int base = t * 16;
    // skew: z index = p + 2*(p>>5); for p in [16t,16t+15], p>>5 == t>>1 (constant)
    float* zp = zsh + base + (t & ~1);

    #pragma unroll
    for (int k = 0; k < 8; k++) {
        const int p = base + 2 * k;
        const float x0 = X[3*p+0], y0 = X[3*p+1], z0 = X[3*p+2];
        const float x1 = X[3*p+3], y1 = X[3*p+4], z1 = X[3*p+5];
        xq[k] = f2_pack(x0, x1);
        yq[k] = f2_pack(y0, y1);
        zp[2*k]   = z0;
        zp[2*k+1] = z1;
        pd[2*k]   = 1e10f;
        pd[2*k+1] = 1e10f;
        g_n2[b*N_PTS + p]     = __fadd_rn(__fadd_rn(__fmul_rn(x0,x0), __fmul_rn(y0,y0)), __fmul_rn(z0,z0));
        g_n2[b*N_PTS + p + 1] = __fadd_rn(__fadd_rn(__fmul_rn(x1,x1), __fmul_rn(y1,y1)), __fmul_rn(z1,z1));
    }

    if (t == 0) {
        g_cents[b*NPT] = 0;                       // cents[0] = 0 (scan emits carry first)
        const float cx = X[0], cy = X[1], cz = X[2];
        s_c[0] = cx; s_c[1] = cy; s_c[2] = cz;
        float* o = out_newxyz + (size_t)b * NPT * 3;
        o[0] = cx; o[1] = cy; o[2] = cz;
    }
    __syncthreads();

    for (int it = 0; it < NPT - 1; ++it) {
        const float cx = s_c[0], cy = s_c[1], cz = s_c[2];
        const unsigned long long ncx = f2_pack(-cx, -cx);
        const unsigned long long ncy = f2_pack(-cy, -cy);
        const unsigned long long ncz = f2_pack(-cz, -cz);

        float best = -1.0f;
        int   bidx = 0;

        #pragma unroll
        for (int k = 0; k < 8; k++) {
            const unsigned long long zz = *reinterpret_cast<const unsigned long long*>(zp + 2*k);
            const unsigned long long dx = f2_add(xq[k], ncx);
            const unsigned long long dy = f2_add(yq[k], ncy);
            const unsigned long long dz = f2_add(zz,    ncz);
            const unsigned long long s  =
                f2_add(f2_add(f2_mul(dx, dx), f2_mul(dy, dy)), f2_mul(dz, dz));
            float d0, d1;
            f2_unpack(d0, d1, s);
            const float v0 = fminf(pd[2*k],   d0); pd[2*k]   = v0;
            const float v1 = fminf(pd[2*k+1], d1); pd[2*k+1] = v1;
            if (v0 > best) { best = v0; bidx = base + 2*k; }
            if (v1 > best) { best = v1; bidx = base + 2*k + 1; }
        }

        // warp argmax (max value, tie -> smaller index == first occurrence)
        #pragma unroll
        for (int off = 16; off; off >>= 1) {
            const float ov = __shfl_down_sync(0xffffffffu, best, off);
            const int   oi = __shfl_down_sync(0xffffffffu, bidx, off);
            if (ov > best || (ov == best && oi < bidx)) { best = ov; bidx = oi; }
        }
        if ((t & 31) == 0) { s_val[t >> 5] = best; s_idx[t >> 5] = bidx; }
        __syncthreads();

        if (t < 32) {
            best = s_val[t]; bidx = s_idx[t];
            #pragma unroll
            for (int off = 16; off; off >>= 1) {
                const float ov = __shfl_down_sync(0xffffffffu, best, off);
                const int   oi = __shfl_down_sync(0xffffffffu, bidx, off);
                if (ov > best || (ov == best && oi < bidx)) { best = ov; bidx = oi; }
            }
            if (t == 0) {
                const int w = bidx;
                g_cents[b*NPT + it + 1] = w;
                const float wx = X[3*w], wy = X[3*w+1], wz = X[3*w+2];
                s_c[0] = wx; s_c[1] = wy; s_c[2] = wz;
                float* o = out_newxyz + ((size_t)b * NPT + it + 1) * 3;
                o[0] = wx; o[1] = wy; o[2] = wz;
            }
        }
        __syncthreads();
    }
}

// =================================================================================
// Kernel 2: ball query — one warp per centroid, early exit after K found.
// Distance matches the reference's expanded form: d = ((-2*dot) + s2) + n2
// (dot as fma chain like a GEMM; s2, n2 as square-then-sum plain ops).
// Qualify iff !(d > r^2); first K in index order; pad with first; guard clamp.
// =================================================================================
__global__ void __launch_bounds__(256)
ball_kernel(const float* __restrict__ xyz, const float* __restrict__ newxyz)
{
    const int wig    = (blockIdx.x * 256 + threadIdx.x) >> 5;   // global warp id = b*512+s
    const int lane   = threadIdx.x & 31;
    const int wlocal = threadIdx.x >> 5;
    __shared__ int sid[8][KNB];

    const int b = wig >> 9;
    const float* C = newxyz + (size_t)wig * 3;
    const float cx = C[0], cy = C[1], cz = C[2];
    const float s2 = __fadd_rn(__fadd_rn(__fmul_rn(cx,cx), __fmul_rn(cy,cy)), __fmul_rn(cz,cz));

    const float* X  = xyz  + (size_t)b * N_PTS * 3;
    const float* NN = g_n2 + (size_t)b * N_PTS;

    int cnt = 0;
    for (int basep = 0; basep < N_PTS && cnt < KNB; basep += 32) {
        const int p = basep + lane;
        const float x = X[3*p], y = X[3*p+1], z = X[3*p+2];
        float dot = __fmul_rn(cx, x);
        dot = __fmaf_rn(cy, y, dot);
        dot = __fmaf_rn(cz, z, dot);
        const float d = __fadd_rn(__fadd_rn(__fmul_rn(-2.0f, dot), s2), NN[p]);
        const bool q = !(d > R2);
        const unsigned m = __ballot_sync(0xffffffffu, q);
        const int pos = cnt + __popc(m & ((1u << lane) - 1u));
        if (q && pos < KNB) sid[wlocal][pos] = p;
        cnt += __popc(m);
    }
    __syncwarp();

    const int first = (cnt > 0) ? sid[wlocal][0] : (N_PTS - 1);  // (cnt==0 impossible: self qualifies)
    const int v = (lane < cnt) ? sid[wlocal][lane] : first;
    g_idx[(size_t)wig * KNB + lane] = v;
}

// =================================================================================
// Kernel 3: masked max pool — one block per (b,s), thread c over 128 channels,
// 32 independent gathered loads per thread (features array is L2-resident).
// =================================================================================
__global__ void __launch_bounds__(128)
pool_kernel(const float* __restrict__ feat, float* __restrict__ out)
{
    const int g = blockIdx.x;             // b*512 + s
    const int c = threadIdx.x;
    const int b = g >> 9;
    const int s = g & 511;

    __shared__ int nb[KNB];
    if (c < KNB) nb[c] = g_idx[(size_t)g * KNB + c];
    __syncthreads();

    const float* F = feat + ((size_t)b * NCH + c) * N_PTS;

    float m0 = __ldg(F + nb[0]);
    float m1 = __ldg(F + nb[1]);
    float m2 = __ldg(F + nb[2]);
    float m3 = __ldg(F + nb[3]);
    #pragma unroll
    for (int k = 4; k < KNB; k += 4) {
        m0 = fmaxf(m0, __ldg(F + nb[k]));
        m1 = fmaxf(m1, __ldg(F + nb[k+1]));
        m2 = fmaxf(m2, __ldg(F + nb[k+2]));
        m3 = fmaxf(m3, __ldg(F + nb[k+3]));
    }
    const float m = fmaxf(fmaxf(m0, m1), fmaxf(m2, m3));

    out[(size_t)B_SZ*NPT*3 + ((size_t)b * NCH + c) * NPT + s] = m;
}

// =================================================================================
extern "C" void kernel_launch(void* const* d_in, const int* in_sizes, int n_in,
                              void* d_out, int out_size)
{
    const float* xyz  = (const float*)d_in[0];   // (8, 16384, 3) fp32
    const float* feat = (const float*)d_in[1];   // (8, 128, 16384) fp32
    float* out = (float*)d_out;                  // new_xyz (12288) ++ sub_features (524288)

    const int zsmem = (N_PTS + 2 * (N_PTS / 32)) * (int)sizeof(float);  // 69632 B
    cudaFuncSetAttribute(fps_kernel, cudaFuncAttributeMaxDynamicSharedMemorySize, zsmem);

    fps_kernel <<<B_SZ, 1024, zsmem>>>(xyz, out);
    ball_kernel<<<(B_SZ * NPT * 32) / 256, 256>>>(xyz, out);
    pool_kernel<<<B_SZ * NPT, 128>>>(feat, out);
}